// round 1
// baseline (speedup 1.0000x reference)
#include <cuda_runtime.h>
#include <math.h>

#define SEQ     4096
#define BATCH   2
#define ROWS    (BATCH*SEQ)     // 8192
#define DIMK    2048
#define D_INNER 4096
#define NHEADS  64
#define NPROJ   8480            // 8384 (in_proj) + 32 (theta) + 64 (lambda)
#define OFF_Z   0
#define OFF_XC  4096
#define OFF_B   8192
#define OFF_C   8256
#define OFF_DT  8320
#define OFF_TH  8384
#define OFF_LAM 8416
#define NCHUNK  64
#define RMS_EPS 1.1920929e-07f

// ---------------- device scratch (no allocation allowed) ----------------
__device__ float g_W [NPROJ * DIMK];               // dequant combined in-proj weights
__device__ float g_Wo[DIMK * D_INNER];             // dequant out-proj weights
__device__ float g_P [ROWS * NPROJ];               // projection output (278MB)
__device__ float g_Bv[ROWS * 64];                  // B after rmsnorm+bias (then rope, in place)
__device__ float g_Cv[ROWS * 64];
__device__ float g_Ad[ROWS * 64];                  // A_disc
__device__ float g_ga[ROWS * 64];                  // gamma
__device__ float g_be[ROWS * 64];                  // beta
__device__ float g_td[ROWS * 32];                  // theta*dt_avg, becomes angles in place
__device__ float g_Y [ROWS * D_INNER];             // Y_diag -> gated Y -> normalized Y
__device__ float g_S [BATCH * NCHUNK * NHEADS * 64 * 64]; // states -> inter states (in place)
__device__ float g_eA[BATCH * NCHUNK * NHEADS * 64];      // exp(A_cs[l]) per chunk
__device__ float g_cd[BATCH * NCHUNK * NHEADS];           // chunk decay exp(A_cs[-1])

__device__ __forceinline__ float siluf(float x) { return x / (1.f + expf(-x)); }

// ---------------- fq4 dequantization: 1 warp per group of 128 ----------------
__global__ void k_dequant(const float* __restrict__ src, float* __restrict__ dst, int ngroups)
{
    int g = blockIdx.x * 4 + (threadIdx.x >> 5);
    if (g >= ngroups) return;
    int lane = threadIdx.x & 31;
    const float* s = src + (size_t)g * 128;
    float v[4];
    float m = 0.f;
#pragma unroll
    for (int i = 0; i < 4; i++) { v[i] = s[lane + 32*i]; m = fmaxf(m, fabsf(v[i])); }
#pragma unroll
    for (int o = 16; o; o >>= 1) m = fmaxf(m, __shfl_xor_sync(0xffffffffu, m, o));
    float scale = fmaxf(m, 1e-10f) / 7.0f;
    float* o = dst + (size_t)g * 128;
#pragma unroll
    for (int i = 0; i < 4; i++) {
        float q = rintf(v[i] / scale);
        q = fminf(fmaxf(q, -8.f), 7.f);
        o[lane + 32*i] = q * scale;
    }
}

// ---------------- fp32 SGEMM: C[M,N] = A[M,K] * B[N,K]^T ----------------
// 128x128 tile, BK=8, 256 threads, 8x8 microtile
__launch_bounds__(256)
__global__ void k_gemm(const float* __restrict__ A, const float* __restrict__ B,
                       float* __restrict__ C, int M, int N, int K)
{
    __shared__ float As[8][128];
    __shared__ float Bs[8][128];
    const int m0 = blockIdx.x * 128;
    const int n0 = blockIdx.y * 128;
    const int tid = threadIdx.x;
    const int tx = tid & 15, ty = tid >> 4;
    const int lrow = tid >> 1, lk = (tid & 1) * 4;

    const float* Ap = A + (size_t)(m0 + lrow) * K + lk;
    const float* Bp = B + (size_t)(n0 + lrow) * K + lk;
    const bool bok = (n0 + lrow) < N;

    float acc[8][8];
#pragma unroll
    for (int i = 0; i < 8; i++)
#pragma unroll
        for (int j = 0; j < 8; j++) acc[i][j] = 0.f;

    for (int k0 = 0; k0 < K; k0 += 8) {
        float4 a = *(const float4*)(Ap + k0);
        float4 b = bok ? *(const float4*)(Bp + k0) : make_float4(0.f,0.f,0.f,0.f);
        As[lk+0][lrow] = a.x; As[lk+1][lrow] = a.y; As[lk+2][lrow] = a.z; As[lk+3][lrow] = a.w;
        Bs[lk+0][lrow] = b.x; Bs[lk+1][lrow] = b.y; Bs[lk+2][lrow] = b.z; Bs[lk+3][lrow] = b.w;
        __syncthreads();
#pragma unroll
        for (int kk = 0; kk < 8; kk++) {
            float ar[8], br[8];
            *(float4*)(ar)     = *(const float4*)&As[kk][ty*8];
            *(float4*)(ar + 4) = *(const float4*)&As[kk][ty*8 + 4];
            *(float4*)(br)     = *(const float4*)&Bs[kk][tx*8];
            *(float4*)(br + 4) = *(const float4*)&Bs[kk][tx*8 + 4];
#pragma unroll
            for (int i = 0; i < 8; i++)
#pragma unroll
                for (int j = 0; j < 8; j++)
                    acc[i][j] = fmaf(ar[i], br[j], acc[i][j]);
        }
        __syncthreads();
    }
#pragma unroll
    for (int i = 0; i < 8; i++) {
        int m = m0 + ty*8 + i;
        float* Cr = C + (size_t)m * N + n0 + tx*8;
#pragma unroll
        for (int j = 0; j < 8; j++) {
            int n = n0 + tx*8 + j;
            if (n < N) Cr[j] = acc[i][j];
        }
    }
}

// ---------------- pointwise epilogue per (b,l) row: 64 threads ----------------
__global__ void k_point(const float* __restrict__ Bb, const float* __restrict__ Cb,
                        const float* __restrict__ Alog, const float* __restrict__ dtb)
{
    int row = blockIdx.x;
    int t = threadIdx.x;          // 64 threads
    const float* pr = g_P + (size_t)row * NPROJ;
    __shared__ float red[6];

    float dtr = pr[OFF_DT + t] + dtb[t];
    float dt = (dtr > 20.f) ? dtr : log1pf(expf(dtr));     // softplus
    float Ad = -expf(Alog[t]) * dt;
    float lam = 1.f / (1.f + expf(-pr[OFF_LAM + t]));
    g_Ad[row*64 + t] = Ad;
    g_ga[row*64 + t] = lam * dt;
    g_be[row*64 + t] = (1.f - lam) * dt * expf(Ad);

    float bv = pr[OFF_B + t];
    float cv = pr[OFF_C + t];

    float s0 = dt, s1 = bv*bv, s2 = cv*cv;
#pragma unroll
    for (int o = 16; o; o >>= 1) {
        s0 += __shfl_xor_sync(0xffffffffu, s0, o);
        s1 += __shfl_xor_sync(0xffffffffu, s1, o);
        s2 += __shfl_xor_sync(0xffffffffu, s2, o);
    }
    int w = t >> 5;
    if ((t & 31) == 0) { red[w*3+0] = s0; red[w*3+1] = s1; red[w*3+2] = s2; }
    __syncthreads();
    float dt_avg = (red[0] + red[3]) * (1.f/64.f);
    float rb = rsqrtf((red[1] + red[4]) * (1.f/64.f) + RMS_EPS);
    float rc = rsqrtf((red[2] + red[5]) * (1.f/64.f) + RMS_EPS);

    g_Bv[row*64 + t] = bv * rb + Bb[t];
    g_Cv[row*64 + t] = cv * rc + Cb[t];
    if (t < 32) g_td[row*32 + t] = pr[OFF_TH + t] * dt_avg;
}

// ---------------- cumsum of theta*dt_avg over L per (b, n): angles ----------------
__global__ void k_scan()
{
    int b = blockIdx.x >> 5;
    int n = blockIdx.x & 31;
    int tid = threadIdx.x;        // 256
    __shared__ float ps[256];
    float loc[16];
    float run = 0.f;
    int base = (b*SEQ + tid*16) * 32 + n;
#pragma unroll
    for (int j = 0; j < 16; j++) { run += g_td[base + j*32]; loc[j] = run; }
    ps[tid] = run;
    __syncthreads();
#pragma unroll
    for (int o = 1; o < 256; o <<= 1) {
        float v = (tid >= o) ? ps[tid - o] : 0.f;
        __syncthreads();
        ps[tid] += v;
        __syncthreads();
    }
    float off = (tid > 0) ? ps[tid - 1] : 0.f;
#pragma unroll
    for (int j = 0; j < 16; j++) g_td[base + j*32] = loc[j] + off;
}

// ---------------- rope on B and C (in place) ----------------
__global__ void k_rope()
{
    int row = blockIdx.x;
    int t = threadIdx.x;          // 32
    float a = g_td[row*32 + t];
    float ca = cosf(a), sa = sinf(a);
    float br = g_Bv[row*64 + t], bi = g_Bv[row*64 + 32 + t];
    g_Bv[row*64 + t]      = br*ca - bi*sa;
    g_Bv[row*64 + 32 + t] = br*sa + bi*ca;
    float cr = g_Cv[row*64 + t], ci = g_Cv[row*64 + 32 + t];
    g_Cv[row*64 + t]      = cr*ca - ci*sa;
    g_Cv[row*64 + 32 + t] = cr*sa + ci*ca;
}

// ---------------- intra-chunk: Y_diag + per-chunk states; one CTA per (b,c,h) ----------------
// dynamic smem layout (floats): sX[64][68], sB[64][68], sBT[64][68], sCT[64][68], sGT[64][68], sA[64], sW[64]
#define SM_CHUNK_BYTES ((4352*5 + 128) * 4)
__launch_bounds__(256)
__global__ void k_chunk()
{
    extern __shared__ float sm[];
    float* sX  = sm;
    float* sB  = sm + 4352;
    float* sBT = sm + 8704;
    float* sCT = sm + 13056;
    float* sGT = sm + 17408;
    float* sA  = sm + 21760;
    float* sW  = sm + 21824;

    const int h = blockIdx.x, c = blockIdx.y, b = blockIdx.z;
    const int tid = threadIdx.x;

    // cumsum of A_disc over the chunk (Hillis-Steele, 64 lanes)
    if (tid < 64) {
        int row_g = b*SEQ + c*64 + tid;
        sA[tid] = g_Ad[row_g*64 + h];
    }
    __syncthreads();
#pragma unroll
    for (int o = 1; o < 64; o <<= 1) {
        float v = (tid < 64 && tid >= o) ? sA[tid - o] : 0.f;
        __syncthreads();
        if (tid < 64) sA[tid] += v;
        __syncthreads();
    }
    float Alast = sA[63];
    if (tid < 64) {
        sW[tid] = expf(Alast - sA[tid]);                           // decay_states
        g_eA[((b*NCHUNK + c)*NHEADS + h)*64 + tid] = expf(sA[tid]); // exp(A_cs) for Y_off
    }
    if (tid == 0) g_cd[(b*NCHUNK + c)*NHEADS + h] = expf(Alast);

    // load X (built on the fly), B, B^T, C^T
#pragma unroll
    for (int it = 0; it < 4; it++) {
        int idx = tid + it*256;
        int l = idx >> 4;
        int p4 = (idx & 15) << 2;
        int row_g = b*SEQ + c*64 + l;
        const float* xp = g_P + (size_t)row_g*NPROJ + OFF_XC + h*64 + p4;
        float4 xc = *(const float4*)xp;
        float ga = g_ga[row_g*64 + h];
        float be = g_be[row_g*64 + h];
        float4 xv;
        xv.x = siluf(xc.x)*ga; xv.y = siluf(xc.y)*ga; xv.z = siluf(xc.z)*ga; xv.w = siluf(xc.w)*ga;
        if (c*64 + l > 0) {
            float4 xq = *(const float4*)(xp - NPROJ);
            xv.x += siluf(xq.x)*be; xv.y += siluf(xq.y)*be; xv.z += siluf(xq.z)*be; xv.w += siluf(xq.w)*be;
        }
        *(float4*)&sX[l*68 + p4] = xv;
        float4 bb = *(const float4*)&g_Bv[row_g*64 + p4];
        *(float4*)&sB[l*68 + p4] = bb;
        sBT[(p4+0)*68 + l] = bb.x; sBT[(p4+1)*68 + l] = bb.y;
        sBT[(p4+2)*68 + l] = bb.z; sBT[(p4+3)*68 + l] = bb.w;
        float4 cc = *(const float4*)&g_Cv[row_g*64 + p4];
        sCT[(p4+0)*68 + l] = cc.x; sCT[(p4+1)*68 + l] = cc.y;
        sCT[(p4+2)*68 + l] = cc.z; sCT[(p4+3)*68 + l] = cc.w;
    }
    __syncthreads();

    const int ti = tid >> 4, tj = tid & 15;

    // G[l][s] = (C_l . B_s) * exp(Acs[l]-Acs[s]) masked to s<=l, stored transposed
    {
        const int l0 = ti*4, s0 = tj*4;
        float acc[4][4];
#pragma unroll
        for (int i = 0; i < 4; i++)
#pragma unroll
            for (int j = 0; j < 4; j++) acc[i][j] = 0.f;
#pragma unroll
        for (int n = 0; n < 64; n++) {
            float4 cl = *(const float4*)&sCT[n*68 + l0];
            float4 bs = *(const float4*)&sBT[n*68 + s0];
            float clv[4] = {cl.x, cl.y, cl.z, cl.w};
            float bsv[4] = {bs.x, bs.y, bs.z, bs.w};
#pragma unroll
            for (int i = 0; i < 4; i++)
#pragma unroll
                for (int j = 0; j < 4; j++)
                    acc[i][j] = fmaf(clv[i], bsv[j], acc[i][j]);
        }
        float al[4];
#pragma unroll
        for (int i = 0; i < 4; i++) al[i] = sA[l0 + i];
#pragma unroll
        for (int j = 0; j < 4; j++) {
            int s = s0 + j;
            float as = sA[s];
#pragma unroll
            for (int i = 0; i < 4; i++) {
                int l = l0 + i;
                sGT[s*68 + l] = (s <= l) ? acc[i][j] * expf(al[i] - as) : 0.f;
            }
        }
    }
    __syncthreads();

    // Y_diag = G @ X
    {
        const int l0 = ti*4, p0 = tj*4;
        float acc[4][4];
#pragma unroll
        for (int i = 0; i < 4; i++)
#pragma unroll
            for (int j = 0; j < 4; j++) acc[i][j] = 0.f;
#pragma unroll
        for (int s = 0; s < 64; s++) {
            float4 gt = *(const float4*)&sGT[s*68 + l0];
            float4 xr = *(const float4*)&sX[s*68 + p0];
            float gv[4] = {gt.x, gt.y, gt.z, gt.w};
            float xvv[4] = {xr.x, xr.y, xr.z, xr.w};
#pragma unroll
            for (int i = 0; i < 4; i++)
#pragma unroll
                for (int j = 0; j < 4; j++)
                    acc[i][j] = fmaf(gv[i], xvv[j], acc[i][j]);
        }
#pragma unroll
        for (int i = 0; i < 4; i++) {
            int row_g = b*SEQ + c*64 + l0 + i;
            *(float4*)&g_Y[(size_t)row_g*D_INNER + h*64 + p0] =
                make_float4(acc[i][0], acc[i][1], acc[i][2], acc[i][3]);
        }
    }

    // states[p][n] = sum_l decay_l * X[l][p] * B[l][n]
    {
        const int p0 = ti*4, n0 = tj*4;
        float acc[4][4];
#pragma unroll
        for (int i = 0; i < 4; i++)
#pragma unroll
            for (int j = 0; j < 4; j++) acc[i][j] = 0.f;
#pragma unroll
        for (int l = 0; l < 64; l++) {
            float w = sW[l];
            float4 xr = *(const float4*)&sX[l*68 + p0];
            float4 br = *(const float4*)&sB[l*68 + n0];
            float wx[4] = {w*xr.x, w*xr.y, w*xr.z, w*xr.w};
            float bvv[4] = {br.x, br.y, br.z, br.w};
#pragma unroll
            for (int i = 0; i < 4; i++)
#pragma unroll
                for (int j = 0; j < 4; j++)
                    acc[i][j] = fmaf(wx[i], bvv[j], acc[i][j]);
        }
        size_t base = (size_t)((b*NCHUNK + c)*NHEADS + h) * 4096;
#pragma unroll
        for (int i = 0; i < 4; i++)
            *(float4*)&g_S[base + (p0 + i)*64 + n0] =
                make_float4(acc[i][0], acc[i][1], acc[i][2], acc[i][3]);
    }
}

// ---------------- inter-chunk scan: g_S becomes "state entering chunk c" ----------------
__global__ void k_cscan()
{
    int b = blockIdx.x >> 6;
    int h = blockIdx.x & 63;
    int tid = threadIdx.x;        // 256, each owns 16 contiguous state elems
    float s[16];
#pragma unroll
    for (int i = 0; i < 16; i++) s[i] = 0.f;
    for (int c = 0; c < NCHUNK; c++) {
        size_t base = (size_t)((b*NCHUNK + c)*NHEADS + h) * 4096 + tid*16;
        float cd = g_cd[(b*NCHUNK + c)*NHEADS + h];
        float4 t0 = *(const float4*)&g_S[base + 0];
        float4 t1 = *(const float4*)&g_S[base + 4];
        float4 t2 = *(const float4*)&g_S[base + 8];
        float4 t3 = *(const float4*)&g_S[base + 12];
        *(float4*)&g_S[base + 0]  = make_float4(s[0],  s[1],  s[2],  s[3]);
        *(float4*)&g_S[base + 4]  = make_float4(s[4],  s[5],  s[6],  s[7]);
        *(float4*)&g_S[base + 8]  = make_float4(s[8],  s[9],  s[10], s[11]);
        *(float4*)&g_S[base + 12] = make_float4(s[12], s[13], s[14], s[15]);
        s[0]  = fmaf(cd, s[0],  t0.x); s[1]  = fmaf(cd, s[1],  t0.y);
        s[2]  = fmaf(cd, s[2],  t0.z); s[3]  = fmaf(cd, s[3],  t0.w);
        s[4]  = fmaf(cd, s[4],  t1.x); s[5]  = fmaf(cd, s[5],  t1.y);
        s[6]  = fmaf(cd, s[6],  t1.z); s[7]  = fmaf(cd, s[7],  t1.w);
        s[8]  = fmaf(cd, s[8],  t2.x); s[9]  = fmaf(cd, s[9],  t2.y);
        s[10] = fmaf(cd, s[10], t2.z); s[11] = fmaf(cd, s[11], t2.w);
        s[12] = fmaf(cd, s[12], t3.x); s[13] = fmaf(cd, s[13], t3.y);
        s[14] = fmaf(cd, s[14], t3.z); s[15] = fmaf(cd, s[15], t3.w);
    }
}

// ---------------- Y_off + D skip + z gating ----------------
__launch_bounds__(256)
__global__ void k_off(const float* __restrict__ Dp)
{
    __shared__ float sST[64*68];
    __shared__ float sCT[64*68];
    const int h = blockIdx.x, c = blockIdx.y, b = blockIdx.z;
    const int tid = threadIdx.x;
    size_t sbase = (size_t)((b*NCHUNK + c)*NHEADS + h) * 4096;
#pragma unroll
    for (int it = 0; it < 4; it++) {
        int idx = tid + it*256;
        int r = idx >> 4;
        int n4 = (idx & 15) << 2;
        float4 sv = *(const float4*)&g_S[sbase + r*64 + n4];
        sST[(n4+0)*68 + r] = sv.x; sST[(n4+1)*68 + r] = sv.y;
        sST[(n4+2)*68 + r] = sv.z; sST[(n4+3)*68 + r] = sv.w;
        int row_g = b*SEQ + c*64 + r;
        float4 cv = *(const float4*)&g_Cv[row_g*64 + n4];
        sCT[(n4+0)*68 + r] = cv.x; sCT[(n4+1)*68 + r] = cv.y;
        sCT[(n4+2)*68 + r] = cv.z; sCT[(n4+3)*68 + r] = cv.w;
    }
    __syncthreads();
    const int ti = tid >> 4, tj = tid & 15;
    const int l0 = ti*4, p0 = tj*4;
    float acc[4][4];
#pragma unroll
    for (int i = 0; i < 4; i++)
#pragma unroll
        for (int j = 0; j < 4; j++) acc[i][j] = 0.f;
#pragma unroll
    for (int n = 0; n < 64; n++) {
        float4 cl = *(const float4*)&sCT[n*68 + l0];
        float4 sp = *(const float4*)&sST[n*68 + p0];
        float clv[4] = {cl.x, cl.y, cl.z, cl.w};
        float spv[4] = {sp.x, sp.y, sp.z, sp.w};
#pragma unroll
        for (int i = 0; i < 4; i++)
#pragma unroll
            for (int j = 0; j < 4; j++)
                acc[i][j] = fmaf(clv[i], spv[j], acc[i][j]);
    }
    float Dh = Dp[h];
#pragma unroll
    for (int i = 0; i < 4; i++) {
        int l = l0 + i;
        int row_g = b*SEQ + c*64 + l;
        float e = g_eA[((b*NCHUNK + c)*NHEADS + h)*64 + l];
        const float* pr = g_P + (size_t)row_g*NPROJ;
        float4 xc = *(const float4*)&pr[OFF_XC + h*64 + p0];
        float4 zz = *(const float4*)&pr[OFF_Z  + h*64 + p0];
        float* yp = &g_Y[(size_t)row_g*D_INNER + h*64 + p0];
        float4 yd = *(const float4*)yp;
        float4 o;
        o.x = (yd.x + e*acc[i][0] + Dh*siluf(xc.x)) * siluf(zz.x);
        o.y = (yd.y + e*acc[i][1] + Dh*siluf(xc.y)) * siluf(zz.y);
        o.z = (yd.z + e*acc[i][2] + Dh*siluf(xc.z)) * siluf(zz.z);
        o.w = (yd.w + e*acc[i][3] + Dh*siluf(xc.w)) * siluf(zz.w);
        *(float4*)yp = o;
    }
}

// ---------------- rmsnorm over 4096 per row, in place ----------------
__global__ void k_rms()
{
    int row = blockIdx.x;
    int tid = threadIdx.x;        // 256
    float* Yp = g_Y + (size_t)row * D_INNER;
    float4 v[4];
    float ss = 0.f;
#pragma unroll
    for (int i = 0; i < 4; i++) {
        v[i] = *(const float4*)&Yp[tid*16 + i*4];
        ss += v[i].x*v[i].x + v[i].y*v[i].y + v[i].z*v[i].z + v[i].w*v[i].w;
    }
#pragma unroll
    for (int o = 16; o; o >>= 1) ss += __shfl_xor_sync(0xffffffffu, ss, o);
    __shared__ float red[8];
    if ((tid & 31) == 0) red[tid >> 5] = ss;
    __syncthreads();
    float tot = 0.f;
#pragma unroll
    for (int i = 0; i < 8; i++) tot += red[i];
    float r = rsqrtf(tot * (1.f/4096.f) + RMS_EPS);
#pragma unroll
    for (int i = 0; i < 4; i++) {
        float4 o = make_float4(v[i].x*r, v[i].y*r, v[i].z*r, v[i].w*r);
        *(float4*)&Yp[tid*16 + i*4] = o;
    }
}

// ---------------- launcher ----------------
extern "C" void kernel_launch(void* const* d_in, const int* in_sizes, int n_in,
                              void* d_out, int out_size)
{
    const float* x    = (const float*)d_in[0];
    const float* Win  = (const float*)d_in[1];
    const float* Wth  = (const float*)d_in[2];
    const float* Wla  = (const float*)d_in[3];
    const float* Wout = (const float*)d_in[4];
    const float* Bb   = (const float*)d_in[5];
    const float* Cb   = (const float*)d_in[6];
    const float* Alog = (const float*)d_in[7];
    const float* Dp   = (const float*)d_in[8];
    const float* dtb  = (const float*)d_in[9];
    float* out = (float*)d_out;

    float *pW, *pWo, *pP, *pY;
    cudaGetSymbolAddress((void**)&pW,  g_W);
    cudaGetSymbolAddress((void**)&pWo, g_Wo);
    cudaGetSymbolAddress((void**)&pP,  g_P);
    cudaGetSymbolAddress((void**)&pY,  g_Y);

    cudaFuncSetAttribute(k_chunk, cudaFuncAttributeMaxDynamicSharedMemorySize, SM_CHUNK_BYTES);

    // fq4 dequant (groups of 128 contiguous; rows are 2048 = 16 groups, so
    // concatenating W_in/W_theta/W_lambda preserves group boundaries)
    k_dequant<<<(8384*16 + 3)/4, 128>>>(Win, pW, 8384*16);
    k_dequant<<<(512 + 3)/4,    128>>>(Wth, pW + (size_t)8384*DIMK, 512);
    k_dequant<<<(1024 + 3)/4,   128>>>(Wla, pW + (size_t)8416*DIMK, 1024);
    k_dequant<<<65536/4,        128>>>(Wout, pWo, 65536);

    // fused in-projection (+theta, +lambda) GEMM
    k_gemm<<<dim3(ROWS/128, (NPROJ + 127)/128), 256>>>(x, pW, pP, ROWS, NPROJ, DIMK);

    k_point<<<ROWS, 64>>>(Bb, Cb, Alog, dtb);
    k_scan <<<64, 256>>>();
    k_rope <<<ROWS, 32>>>();

    k_chunk<<<dim3(NHEADS, NCHUNK, BATCH), 256, SM_CHUNK_BYTES>>>();
    k_cscan<<<128, 256>>>();
    k_off  <<<dim3(NHEADS, NCHUNK, BATCH), 256>>>(Dp);

    k_rms<<<ROWS, 256>>>();
    k_gemm<<<dim3(ROWS/128, DIMK/128), 256>>>(pY, pWo, out, ROWS, DIMK, D_INNER);
}

// round 3
// speedup vs baseline: 1.9788x; 1.9788x over previous
#include <cuda_runtime.h>
#include <cuda_bf16.h>
#include <math.h>
#include <stdint.h>

#define SEQ     4096
#define BATCH   2
#define ROWS    (BATCH*SEQ)     // 8192
#define DIMK    2048
#define D_INNER 4096
#define NHEADS  64
#define NPROJ   8480            // 8384 (in_proj) + 32 (theta) + 64 (lambda)
#define NPROJ_PAD 8576          // 67 * 128
#define OFF_Z   0
#define OFF_XC  4096
#define OFF_B   8192
#define OFF_C   8256
#define OFF_DT  8320
#define OFF_TH  8384
#define OFF_LAM 8416
#define NCHUNK  64
#define RMS_EPS 1.1920929e-07f

// ---------------- device scratch (no allocation allowed) ----------------
__device__ __nv_bfloat16 g_Wh [NPROJ_PAD * DIMK];   // fused in-proj weights hi (pad rows stay zero)
__device__ __nv_bfloat16 g_Wl [NPROJ_PAD * DIMK];   // fused in-proj weights lo
__device__ __nv_bfloat16 g_Woh[DIMK * D_INNER];
__device__ __nv_bfloat16 g_Wol[DIMK * D_INNER];
__device__ __nv_bfloat16 g_xh [ROWS * DIMK];
__device__ __nv_bfloat16 g_xl [ROWS * DIMK];
__device__ __nv_bfloat16 g_Yh [ROWS * D_INNER];
__device__ __nv_bfloat16 g_Yl [ROWS * D_INNER];
__device__ float g_P [ROWS * NPROJ];                // projection output
__device__ float g_Bv[ROWS * 64];
__device__ float g_Cv[ROWS * 64];
__device__ float g_Ad[ROWS * 64];
__device__ float g_ga[ROWS * 64];
__device__ float g_be[ROWS * 64];
__device__ float g_td[ROWS * 32];
__device__ float g_Y [ROWS * D_INNER];
__device__ float g_S [BATCH * NCHUNK * NHEADS * 64 * 64];
__device__ float g_eA[BATCH * NCHUNK * NHEADS * 64];
__device__ float g_cd[BATCH * NCHUNK * NHEADS];

__device__ __forceinline__ float siluf(float x) { return x / (1.f + expf(-x)); }

__device__ __forceinline__ uint32_t s2u(const void* p) {
    uint32_t a;
    asm("{ .reg .u64 t; cvta.to.shared.u64 t, %1; cvt.u32.u64 %0, t; }" : "=r"(a) : "l"(p));
    return a;
}

// ================= bf16x3 emulated-fp32 GEMM via mma.sync =================
// C[M,Nw] = A[M,K] * B[N,K]^T, A/B pre-split into bf16 hi/lo.
// CTA 128x128, 8 warps (2x4) of 64x32 warp tiles, K-chunk 32, cp.async double buffer.
#define PADH 40                      // 32 halves + 8 pad
#define ARR_H (128*PADH)             // 5120 halves per sub-tile
#define BUF_H (4*ARR_H)              // Ah,Al,Bh,Bl
#define SMEM_MM_BYTES (2*BUF_H*2)    // 81920 bytes

__device__ __forceinline__ void cpasync16(uint32_t dst, const void* src) {
    asm volatile("cp.async.cg.shared.global [%0], [%1], 16;" :: "r"(dst), "l"(src));
}
#define CP_COMMIT() asm volatile("cp.async.commit_group;" ::: "memory")
#define CP_WAIT1()  asm volatile("cp.async.wait_group 1;" ::: "memory")

#define LDSM4(r0,r1,r2,r3,a) \
    asm volatile("ldmatrix.sync.aligned.m8n8.x4.shared.b16 {%0,%1,%2,%3}, [%4];" \
        : "=r"(r0),"=r"(r1),"=r"(r2),"=r"(r3) : "r"(a))

#define MMA16816(d,a,b0,b1) \
    asm volatile("mma.sync.aligned.m16n8k16.row.col.f32.bf16.bf16.f32 " \
        "{%0,%1,%2,%3}, {%4,%5,%6,%7}, {%8,%9}, {%0,%1,%2,%3};" \
        : "+f"((d)[0]),"+f"((d)[1]),"+f"((d)[2]),"+f"((d)[3]) \
        : "r"((a)[0]),"r"((a)[1]),"r"((a)[2]),"r"((a)[3]),"r"(b0),"r"(b1))

__global__ void __launch_bounds__(256, 1)
k_mm(const __nv_bfloat16* __restrict__ Ah, const __nv_bfloat16* __restrict__ Al,
     const __nv_bfloat16* __restrict__ Bh, const __nv_bfloat16* __restrict__ Bl,
     float* __restrict__ C, int Nw, int Nlim, int K)
{
    extern __shared__ __nv_bfloat16 sh[];
    const uint32_t sb = s2u(sh);
    const int tid  = threadIdx.x;
    const int lane = tid & 31;
    const int wid  = tid >> 5;
    const int m0 = blockIdx.x * 128;
    const int n0 = blockIdx.y * 128;
    const int mw = (wid >> 2) * 64;
    const int nw = (wid & 3) * 32;

    const __nv_bfloat16* srcs[4] = { Ah, Al, Bh, Bl };

    float acc[4][4][4];
#pragma unroll
    for (int i = 0; i < 4; i++)
#pragma unroll
        for (int j = 0; j < 4; j++)
#pragma unroll
            for (int k = 0; k < 4; k++) acc[i][j][k] = 0.f;

    const int NK = K >> 5;

    // fill lambda (macro-style): buf, kc
#define FILL(buf, kc) do {                                                       \
        int kb = (kc) * 32;                                                      \
_Pragma("unroll")                                                                \
        for (int i = 0; i < 8; i++) {                                            \
            int idx = i * 256 + tid;                                             \
            int arr = idx >> 9;                                                  \
            int r   = (idx >> 2) & 127;                                          \
            int c   = idx & 3;                                                   \
            int grow = (arr < 2) ? (m0 + r) : (n0 + r);                          \
            const __nv_bfloat16* sp = srcs[arr] + (size_t)grow * K + kb + c * 8; \
            uint32_t dp = sb + ((buf) * BUF_H + arr * ARR_H + r * PADH + c * 8) * 2; \
            cpasync16(dp, sp);                                                   \
        }                                                                        \
    } while (0)

    FILL(0, 0);
    CP_COMMIT();

    const int rowoff = (lane & 7) + ((lane >> 3) & 1) * 8;
    const int coloff = (lane >> 4) * 8;

    for (int kc = 0; kc < NK; kc++) {
        const int buf = kc & 1;
        if (kc + 1 < NK) FILL(buf ^ 1, kc + 1);
        CP_COMMIT();
        CP_WAIT1();
        __syncthreads();

#pragma unroll
        for (int kk = 0; kk < 2; kk++) {
            uint32_t afr[2][4][4];
            uint32_t bfr[2][2][4];
#pragma unroll
            for (int hl = 0; hl < 2; hl++) {
#pragma unroll
                for (int mi = 0; mi < 4; mi++) {
                    uint32_t a = sb + (buf * BUF_H + hl * ARR_H +
                        (mw + mi * 16 + rowoff) * PADH + kk * 16 + coloff) * 2;
                    LDSM4(afr[hl][mi][0], afr[hl][mi][1], afr[hl][mi][2], afr[hl][mi][3], a);
                }
#pragma unroll
                for (int nj = 0; nj < 2; nj++) {
                    uint32_t a = sb + (buf * BUF_H + (2 + hl) * ARR_H +
                        (nw + nj * 16 + rowoff) * PADH + kk * 16 + coloff) * 2;
                    LDSM4(bfr[hl][nj][0], bfr[hl][nj][1], bfr[hl][nj][2], bfr[hl][nj][3], a);
                }
            }
            // term 0: Ah*Bh, term 1: Al*Bh, term 2: Ah*Bl
#pragma unroll
            for (int term = 0; term < 3; term++) {
                const int ahl = (term == 1) ? 1 : 0;
                const int bhl = (term == 2) ? 1 : 0;
#pragma unroll
                for (int mi = 0; mi < 4; mi++)
#pragma unroll
                    for (int ni = 0; ni < 4; ni++) {
                        int nj = ni >> 1, s = ni & 1;
                        MMA16816(acc[mi][ni], afr[ahl][mi],
                                 bfr[bhl][nj][s], bfr[bhl][nj][s + 2]);
                    }
            }
        }
        __syncthreads();
    }

    // epilogue
    const int r0 = lane >> 2, c0 = (lane & 3) * 2;
#pragma unroll
    for (int mi = 0; mi < 4; mi++) {
#pragma unroll
        for (int ni = 0; ni < 4; ni++) {
            int m = m0 + mw + mi * 16 + r0;
            int n = n0 + nw + ni * 8 + c0;
            if (n < Nlim) {
                *(float2*)&C[(size_t)m * Nw + n]       = make_float2(acc[mi][ni][0], acc[mi][ni][1]);
                *(float2*)&C[(size_t)(m + 8) * Nw + n] = make_float2(acc[mi][ni][2], acc[mi][ni][3]);
            }
        }
    }
#undef FILL
}

// ---------------- fq4 dequantization -> bf16 hi/lo: 1 warp per group of 128 ----------------
__global__ void k_dequant(const float* __restrict__ src, __nv_bfloat16* __restrict__ dh,
                          __nv_bfloat16* __restrict__ dl, int ngroups)
{
    int g = blockIdx.x * 4 + (threadIdx.x >> 5);
    if (g >= ngroups) return;
    int lane = threadIdx.x & 31;
    const float* s = src + (size_t)g * 128;
    float v[4];
    float m = 0.f;
#pragma unroll
    for (int i = 0; i < 4; i++) { v[i] = s[lane + 32*i]; m = fmaxf(m, fabsf(v[i])); }
#pragma unroll
    for (int o = 16; o; o >>= 1) m = fmaxf(m, __shfl_xor_sync(0xffffffffu, m, o));
    float scale = fmaxf(m, 1e-10f) / 7.0f;
#pragma unroll
    for (int i = 0; i < 4; i++) {
        float q = rintf(v[i] / scale);
        q = fminf(fmaxf(q, -8.f), 7.f);
        float w = q * scale;
        __nv_bfloat16 h = __float2bfloat16(w);
        dh[(size_t)g * 128 + lane + 32*i] = h;
        dl[(size_t)g * 128 + lane + 32*i] = __float2bfloat16(w - __bfloat162float(h));
    }
}

// ---------------- split fp32 -> bf16 hi/lo ----------------
__global__ void k_split(const float* __restrict__ src, __nv_bfloat16* __restrict__ dh,
                        __nv_bfloat16* __restrict__ dl)
{
    size_t i = ((size_t)blockIdx.x * 256 + threadIdx.x) * 4;
    float4 v = *(const float4*)(src + i);
    float vv[4] = {v.x, v.y, v.z, v.w};
#pragma unroll
    for (int k = 0; k < 4; k++) {
        __nv_bfloat16 h = __float2bfloat16(vv[k]);
        dh[i + k] = h;
        dl[i + k] = __float2bfloat16(vv[k] - __bfloat162float(h));
    }
}

// ---------------- pointwise epilogue per (b,l) row: 64 threads ----------------
__global__ void k_point(const float* __restrict__ Bb, const float* __restrict__ Cb,
                        const float* __restrict__ Alog, const float* __restrict__ dtb)
{
    int row = blockIdx.x;
    int t = threadIdx.x;
    const float* pr = g_P + (size_t)row * NPROJ;
    __shared__ float red[6];

    float dtr = pr[OFF_DT + t] + dtb[t];
    float dt = (dtr > 20.f) ? dtr : log1pf(expf(dtr));
    float Ad = -expf(Alog[t]) * dt;
    float lam = 1.f / (1.f + expf(-pr[OFF_LAM + t]));
    g_Ad[row*64 + t] = Ad;
    g_ga[row*64 + t] = lam * dt;
    g_be[row*64 + t] = (1.f - lam) * dt * expf(Ad);

    float bv = pr[OFF_B + t];
    float cv = pr[OFF_C + t];

    float s0 = dt, s1 = bv*bv, s2 = cv*cv;
#pragma unroll
    for (int o = 16; o; o >>= 1) {
        s0 += __shfl_xor_sync(0xffffffffu, s0, o);
        s1 += __shfl_xor_sync(0xffffffffu, s1, o);
        s2 += __shfl_xor_sync(0xffffffffu, s2, o);
    }
    int w = t >> 5;
    if ((t & 31) == 0) { red[w*3+0] = s0; red[w*3+1] = s1; red[w*3+2] = s2; }
    __syncthreads();
    float dt_avg = (red[0] + red[3]) * (1.f/64.f);
    float rb = rsqrtf((red[1] + red[4]) * (1.f/64.f) + RMS_EPS);
    float rc = rsqrtf((red[2] + red[5]) * (1.f/64.f) + RMS_EPS);

    g_Bv[row*64 + t] = bv * rb + Bb[t];
    g_Cv[row*64 + t] = cv * rc + Cb[t];
    if (t < 32) g_td[row*32 + t] = pr[OFF_TH + t] * dt_avg;
}

// ---------------- cumsum of theta*dt_avg over L per (b, n) ----------------
__global__ void k_scan()
{
    int b = blockIdx.x >> 5;
    int n = blockIdx.x & 31;
    int tid = threadIdx.x;
    __shared__ float ps[256];
    float loc[16];
    float run = 0.f;
    int base = (b*SEQ + tid*16) * 32 + n;
#pragma unroll
    for (int j = 0; j < 16; j++) { run += g_td[base + j*32]; loc[j] = run; }
    ps[tid] = run;
    __syncthreads();
#pragma unroll
    for (int o = 1; o < 256; o <<= 1) {
        float v = (tid >= o) ? ps[tid - o] : 0.f;
        __syncthreads();
        ps[tid] += v;
        __syncthreads();
    }
    float off = (tid > 0) ? ps[tid - 1] : 0.f;
#pragma unroll
    for (int j = 0; j < 16; j++) g_td[base + j*32] = loc[j] + off;
}

// ---------------- rope on B and C (in place) ----------------
__global__ void k_rope()
{
    int row = blockIdx.x;
    int t = threadIdx.x;
    float a = g_td[row*32 + t];
    float ca = cosf(a), sa = sinf(a);
    float br = g_Bv[row*64 + t], bi = g_Bv[row*64 + 32 + t];
    g_Bv[row*64 + t]      = br*ca - bi*sa;
    g_Bv[row*64 + 32 + t] = br*sa + bi*ca;
    float cr = g_Cv[row*64 + t], ci = g_Cv[row*64 + 32 + t];
    g_Cv[row*64 + t]      = cr*ca - ci*sa;
    g_Cv[row*64 + 32 + t] = cr*sa + ci*ca;
}

// ---------------- intra-chunk: Y_diag + per-chunk states ----------------
#define SM_CHUNK_BYTES ((4352*5 + 128) * 4)
__launch_bounds__(256)
__global__ void k_chunk()
{
    extern __shared__ float sm[];
    float* sX  = sm;
    float* sB  = sm + 4352;
    float* sBT = sm + 8704;
    float* sCT = sm + 13056;
    float* sGT = sm + 17408;
    float* sA  = sm + 21760;
    float* sW  = sm + 21824;

    const int h = blockIdx.x, c = blockIdx.y, b = blockIdx.z;
    const int tid = threadIdx.x;

    if (tid < 64) {
        int row_g = b*SEQ + c*64 + tid;
        sA[tid] = g_Ad[row_g*64 + h];
    }
    __syncthreads();
#pragma unroll
    for (int o = 1; o < 64; o <<= 1) {
        float v = (tid < 64 && tid >= o) ? sA[tid - o] : 0.f;
        __syncthreads();
        if (tid < 64) sA[tid] += v;
        __syncthreads();
    }
    float Alast = sA[63];
    if (tid < 64) {
        sW[tid] = expf(Alast - sA[tid]);
        g_eA[((b*NCHUNK + c)*NHEADS + h)*64 + tid] = expf(sA[tid]);
    }
    if (tid == 0) g_cd[(b*NCHUNK + c)*NHEADS + h] = expf(Alast);

#pragma unroll
    for (int it = 0; it < 4; it++) {
        int idx = tid + it*256;
        int l = idx >> 4;
        int p4 = (idx & 15) << 2;
        int row_g = b*SEQ + c*64 + l;
        const float* xp = g_P + (size_t)row_g*NPROJ + OFF_XC + h*64 + p4;
        float4 xc = *(const float4*)xp;
        float ga = g_ga[row_g*64 + h];
        float be = g_be[row_g*64 + h];
        float4 xv;
        xv.x = siluf(xc.x)*ga; xv.y = siluf(xc.y)*ga; xv.z = siluf(xc.z)*ga; xv.w = siluf(xc.w)*ga;
        if (c*64 + l > 0) {
            float4 xq = *(const float4*)(xp - NPROJ);
            xv.x += siluf(xq.x)*be; xv.y += siluf(xq.y)*be; xv.z += siluf(xq.z)*be; xv.w += siluf(xq.w)*be;
        }
        *(float4*)&sX[l*68 + p4] = xv;
        float4 bb = *(const float4*)&g_Bv[row_g*64 + p4];
        *(float4*)&sB[l*68 + p4] = bb;
        sBT[(p4+0)*68 + l] = bb.x; sBT[(p4+1)*68 + l] = bb.y;
        sBT[(p4+2)*68 + l] = bb.z; sBT[(p4+3)*68 + l] = bb.w;
        float4 cc = *(const float4*)&g_Cv[row_g*64 + p4];
        sCT[(p4+0)*68 + l] = cc.x; sCT[(p4+1)*68 + l] = cc.y;
        sCT[(p4+2)*68 + l] = cc.z; sCT[(p4+3)*68 + l] = cc.w;
    }
    __syncthreads();

    const int ti = tid >> 4, tj = tid & 15;

    {
        const int l0 = ti*4, s0 = tj*4;
        float acc[4][4];
#pragma unroll
        for (int i = 0; i < 4; i++)
#pragma unroll
            for (int j = 0; j < 4; j++) acc[i][j] = 0.f;
#pragma unroll
        for (int n = 0; n < 64; n++) {
            float4 cl = *(const float4*)&sCT[n*68 + l0];
            float4 bs = *(const float4*)&sBT[n*68 + s0];
            float clv[4] = {cl.x, cl.y, cl.z, cl.w};
            float bsv[4] = {bs.x, bs.y, bs.z, bs.w};
#pragma unroll
            for (int i = 0; i < 4; i++)
#pragma unroll
                for (int j = 0; j < 4; j++)
                    acc[i][j] = fmaf(clv[i], bsv[j], acc[i][j]);
        }
        float al[4];
#pragma unroll
        for (int i = 0; i < 4; i++) al[i] = sA[l0 + i];
#pragma unroll
        for (int j = 0; j < 4; j++) {
            int s = s0 + j;
            float as = sA[s];
#pragma unroll
            for (int i = 0; i < 4; i++) {
                int l = l0 + i;
                sGT[s*68 + l] = (s <= l) ? acc[i][j] * expf(al[i] - as) : 0.f;
            }
        }
    }
    __syncthreads();

    {
        const int l0 = ti*4, p0 = tj*4;
        float acc[4][4];
#pragma unroll
        for (int i = 0; i < 4; i++)
#pragma unroll
            for (int j = 0; j < 4; j++) acc[i][j] = 0.f;
#pragma unroll
        for (int s = 0; s < 64; s++) {
            float4 gt = *(const float4*)&sGT[s*68 + l0];
            float4 xr = *(const float4*)&sX[s*68 + p0];
            float gv[4] = {gt.x, gt.y, gt.z, gt.w};
            float xvv[4] = {xr.x, xr.y, xr.z, xr.w};
#pragma unroll
            for (int i = 0; i < 4; i++)
#pragma unroll
                for (int j = 0; j < 4; j++)
                    acc[i][j] = fmaf(gv[i], xvv[j], acc[i][j]);
        }
#pragma unroll
        for (int i = 0; i < 4; i++) {
            int row_g = b*SEQ + c*64 + l0 + i;
            *(float4*)&g_Y[(size_t)row_g*D_INNER + h*64 + p0] =
                make_float4(acc[i][0], acc[i][1], acc[i][2], acc[i][3]);
        }
    }

    {
        const int p0 = ti*4, n0 = tj*4;
        float acc[4][4];
#pragma unroll
        for (int i = 0; i < 4; i++)
#pragma unroll
            for (int j = 0; j < 4; j++) acc[i][j] = 0.f;
#pragma unroll
        for (int l = 0; l < 64; l++) {
            float w = sW[l];
            float4 xr = *(const float4*)&sX[l*68 + p0];
            float4 br = *(const float4*)&sB[l*68 + n0];
            float wx[4] = {w*xr.x, w*xr.y, w*xr.z, w*xr.w};
            float bvv[4] = {br.x, br.y, br.z, br.w};
#pragma unroll
            for (int i = 0; i < 4; i++)
#pragma unroll
                for (int j = 0; j < 4; j++)
                    acc[i][j] = fmaf(wx[i], bvv[j], acc[i][j]);
        }
        size_t base = (size_t)((b*NCHUNK + c)*NHEADS + h) * 4096;
#pragma unroll
        for (int i = 0; i < 4; i++)
            *(float4*)&g_S[base + (p0 + i)*64 + n0] =
                make_float4(acc[i][0], acc[i][1], acc[i][2], acc[i][3]);
    }
}

// ---------------- inter-chunk scan ----------------
__global__ void k_cscan()
{
    int b = blockIdx.x >> 6;
    int h = blockIdx.x & 63;
    int tid = threadIdx.x;
    float s[16];
#pragma unroll
    for (int i = 0; i < 16; i++) s[i] = 0.f;
    for (int c = 0; c < NCHUNK; c++) {
        size_t base = (size_t)((b*NCHUNK + c)*NHEADS + h) * 4096 + tid*16;
        float cd = g_cd[(b*NCHUNK + c)*NHEADS + h];
        float4 t0 = *(const float4*)&g_S[base + 0];
        float4 t1 = *(const float4*)&g_S[base + 4];
        float4 t2 = *(const float4*)&g_S[base + 8];
        float4 t3 = *(const float4*)&g_S[base + 12];
        *(float4*)&g_S[base + 0]  = make_float4(s[0],  s[1],  s[2],  s[3]);
        *(float4*)&g_S[base + 4]  = make_float4(s[4],  s[5],  s[6],  s[7]);
        *(float4*)&g_S[base + 8]  = make_float4(s[8],  s[9],  s[10], s[11]);
        *(float4*)&g_S[base + 12] = make_float4(s[12], s[13], s[14], s[15]);
        s[0]  = fmaf(cd, s[0],  t0.x); s[1]  = fmaf(cd, s[1],  t0.y);
        s[2]  = fmaf(cd, s[2],  t0.z); s[3]  = fmaf(cd, s[3],  t0.w);
        s[4]  = fmaf(cd, s[4],  t1.x); s[5]  = fmaf(cd, s[5],  t1.y);
        s[6]  = fmaf(cd, s[6],  t1.z); s[7]  = fmaf(cd, s[7],  t1.w);
        s[8]  = fmaf(cd, s[8],  t2.x); s[9]  = fmaf(cd, s[9],  t2.y);
        s[10] = fmaf(cd, s[10], t2.z); s[11] = fmaf(cd, s[11], t2.w);
        s[12] = fmaf(cd, s[12], t3.x); s[13] = fmaf(cd, s[13], t3.y);
        s[14] = fmaf(cd, s[14], t3.z); s[15] = fmaf(cd, s[15], t3.w);
    }
}

// ---------------- Y_off + D skip + z gating ----------------
__launch_bounds__(256)
__global__ void k_off(const float* __restrict__ Dp)
{
    __shared__ float sST[64*68];
    __shared__ float sCT[64*68];
    const int h = blockIdx.x, c = blockIdx.y, b = blockIdx.z;
    const int tid = threadIdx.x;
    size_t sbase = (size_t)((b*NCHUNK + c)*NHEADS + h) * 4096;
#pragma unroll
    for (int it = 0; it < 4; it++) {
        int idx = tid + it*256;
        int r = idx >> 4;
        int n4 = (idx & 15) << 2;
        float4 sv = *(const float4*)&g_S[sbase + r*64 + n4];
        sST[(n4+0)*68 + r] = sv.x; sST[(n4+1)*68 + r] = sv.y;
        sST[(n4+2)*68 + r] = sv.z; sST[(n4+3)*68 + r] = sv.w;
        int row_g = b*SEQ + c*64 + r;
        float4 cv = *(const float4*)&g_Cv[row_g*64 + n4];
        sCT[(n4+0)*68 + r] = cv.x; sCT[(n4+1)*68 + r] = cv.y;
        sCT[(n4+2)*68 + r] = cv.z; sCT[(n4+3)*68 + r] = cv.w;
    }
    __syncthreads();
    const int ti = tid >> 4, tj = tid & 15;
    const int l0 = ti*4, p0 = tj*4;
    float acc[4][4];
#pragma unroll
    for (int i = 0; i < 4; i++)
#pragma unroll
        for (int j = 0; j < 4; j++) acc[i][j] = 0.f;
#pragma unroll
    for (int n = 0; n < 64; n++) {
        float4 cl = *(const float4*)&sCT[n*68 + l0];
        float4 sp = *(const float4*)&sST[n*68 + p0];
        float clv[4] = {cl.x, cl.y, cl.z, cl.w};
        float spv[4] = {sp.x, sp.y, sp.z, sp.w};
#pragma unroll
        for (int i = 0; i < 4; i++)
#pragma unroll
            for (int j = 0; j < 4; j++)
                acc[i][j] = fmaf(clv[i], spv[j], acc[i][j]);
    }
    float Dh = Dp[h];
#pragma unroll
    for (int i = 0; i < 4; i++) {
        int l = l0 + i;
        int row_g = b*SEQ + c*64 + l;
        float e = g_eA[((b*NCHUNK + c)*NHEADS + h)*64 + l];
        const float* pr = g_P + (size_t)row_g*NPROJ;
        float4 xc = *(const float4*)&pr[OFF_XC + h*64 + p0];
        float4 zz = *(const float4*)&pr[OFF_Z  + h*64 + p0];
        float* yp = &g_Y[(size_t)row_g*D_INNER + h*64 + p0];
        float4 yd = *(const float4*)yp;
        float4 o;
        o.x = (yd.x + e*acc[i][0] + Dh*siluf(xc.x)) * siluf(zz.x);
        o.y = (yd.y + e*acc[i][1] + Dh*siluf(xc.y)) * siluf(zz.y);
        o.z = (yd.z + e*acc[i][2] + Dh*siluf(xc.z)) * siluf(zz.z);
        o.w = (yd.w + e*acc[i][3] + Dh*siluf(xc.w)) * siluf(zz.w);
        *(float4*)yp = o;
    }
}

// ---------------- rmsnorm over 4096 per row -> bf16 hi/lo ----------------
__global__ void k_rms()
{
    int row = blockIdx.x;
    int tid = threadIdx.x;
    const float* Yp = g_Y + (size_t)row * D_INNER;
    float4 v[4];
    float ss = 0.f;
#pragma unroll
    for (int i = 0; i < 4; i++) {
        v[i] = *(const float4*)&Yp[tid*16 + i*4];
        ss += v[i].x*v[i].x + v[i].y*v[i].y + v[i].z*v[i].z + v[i].w*v[i].w;
    }
#pragma unroll
    for (int o = 16; o; o >>= 1) ss += __shfl_xor_sync(0xffffffffu, ss, o);
    __shared__ float red[8];
    if ((tid & 31) == 0) red[tid >> 5] = ss;
    __syncthreads();
    float tot = 0.f;
#pragma unroll
    for (int i = 0; i < 8; i++) tot += red[i];
    float r = rsqrtf(tot * (1.f/4096.f) + RMS_EPS);
    size_t base = (size_t)row * D_INNER + tid*16;
#pragma unroll
    for (int i = 0; i < 4; i++) {
        float vv[4] = {v[i].x*r, v[i].y*r, v[i].z*r, v[i].w*r};
#pragma unroll
        for (int k = 0; k < 4; k++) {
            __nv_bfloat16 h = __float2bfloat16(vv[k]);
            g_Yh[base + i*4 + k] = h;
            g_Yl[base + i*4 + k] = __float2bfloat16(vv[k] - __bfloat162float(h));
        }
    }
}

// ---------------- launcher ----------------
extern "C" void kernel_launch(void* const* d_in, const int* in_sizes, int n_in,
                              void* d_out, int out_size)
{
    const float* x    = (const float*)d_in[0];
    const float* Win  = (const float*)d_in[1];
    const float* Wth  = (const float*)d_in[2];
    const float* Wla  = (const float*)d_in[3];
    const float* Wout = (const float*)d_in[4];
    const float* Bb   = (const float*)d_in[5];
    const float* Cb   = (const float*)d_in[6];
    const float* Alog = (const float*)d_in[7];
    const float* Dp   = (const float*)d_in[8];
    const float* dtb  = (const float*)d_in[9];
    float* out = (float*)d_out;

    __nv_bfloat16 *pWh, *pWl, *pWoh, *pWol, *pxh, *pxl, *pYh, *pYl;
    float *pP;
    cudaGetSymbolAddress((void**)&pWh,  g_Wh);
    cudaGetSymbolAddress((void**)&pWl,  g_Wl);
    cudaGetSymbolAddress((void**)&pWoh, g_Woh);
    cudaGetSymbolAddress((void**)&pWol, g_Wol);
    cudaGetSymbolAddress((void**)&pxh,  g_xh);
    cudaGetSymbolAddress((void**)&pxl,  g_xl);
    cudaGetSymbolAddress((void**)&pYh,  g_Yh);
    cudaGetSymbolAddress((void**)&pYl,  g_Yl);
    cudaGetSymbolAddress((void**)&pP,   g_P);

    cudaFuncSetAttribute(k_chunk, cudaFuncAttributeMaxDynamicSharedMemorySize, SM_CHUNK_BYTES);
    cudaFuncSetAttribute(k_mm,    cudaFuncAttributeMaxDynamicSharedMemorySize, SMEM_MM_BYTES);

    // fq4 dequant -> bf16 hi/lo into fused weight buffer (pad rows stay zero)
    k_dequant<<<(8384*16 + 3)/4, 128>>>(Win, pWh, pWl, 8384*16);
    k_dequant<<<(512 + 3)/4,    128>>>(Wth, pWh + (size_t)8384*DIMK, pWl + (size_t)8384*DIMK, 512);
    k_dequant<<<(1024 + 3)/4,   128>>>(Wla, pWh + (size_t)8416*DIMK, pWl + (size_t)8416*DIMK, 1024);
    k_dequant<<<65536/4,        128>>>(Wout, pWoh, pWol, 65536);

    // split activations
    k_split<<<ROWS*DIMK/1024, 256>>>(x, pxh, pxl);

    // in-projection GEMM: 8192 x 8480 x 2048 (bf16x3 mma.sync)
    k_mm<<<dim3(ROWS/128, NPROJ_PAD/128), 256, SMEM_MM_BYTES>>>(
        pxh, pxl, pWh, pWl, pP, NPROJ, NPROJ, DIMK);

    k_point<<<ROWS, 64>>>(Bb, Cb, Alog, dtb);
    k_scan <<<64, 256>>>();
    k_rope <<<ROWS, 32>>>();

    k_chunk<<<dim3(NHEADS, NCHUNK, BATCH), 256, SM_CHUNK_BYTES>>>();
    k_cscan<<<128, 256>>>();
    k_off  <<<dim3(NHEADS, NCHUNK, BATCH), 256>>>(Dp);

    k_rms<<<ROWS, 256>>>();

    // out-projection GEMM: 8192 x 2048 x 4096 (bf16x3 mma.sync)
    k_mm<<<dim3(ROWS/128, DIMK/128), 256, SMEM_MM_BYTES>>>(
        pYh, pYl, pWoh, pWol, out, DIMK, DIMK, D_INNER);
}

// round 4
// speedup vs baseline: 2.5680x; 1.2977x over previous
#include <cuda_runtime.h>
#include <cuda_bf16.h>
#include <math.h>
#include <stdint.h>

#define SEQ     4096
#define BATCH   2
#define ROWS    (BATCH*SEQ)     // 8192
#define DIMK    2048
#define D_INNER 4096
#define NHEADS  64
#define NPROJ   8480            // 8384 (in_proj) + 32 (theta) + 64 (lambda)
#define NPROJ_PAD 8576          // 67 * 128
#define OFF_Z   0
#define OFF_XC  4096
#define OFF_B   8192
#define OFF_C   8256
#define OFF_DT  8320
#define OFF_TH  8384
#define OFF_LAM 8416
#define NCHUNK  64
#define RMS_EPS 1.1920929e-07f

// ---------------- device scratch (no allocation allowed) ----------------
__device__ __nv_bfloat16 g_Wq [NPROJ_PAD * DIMK];   // fused in-proj q (4-bit ints, exact in bf16)
__device__ float         g_Ws [NPROJ_PAD * 16];     // per-group scales (16 groups of 128 per row)
__device__ __nv_bfloat16 g_Woq[DIMK * D_INNER];     // out-proj q
__device__ float         g_Wos[DIMK * 32];          // out-proj scales (32 groups per row)
__device__ __nv_bfloat16 g_xh [ROWS * DIMK];
__device__ __nv_bfloat16 g_xl [ROWS * DIMK];
__device__ __nv_bfloat16 g_Yh [ROWS * D_INNER];
__device__ __nv_bfloat16 g_Yl [ROWS * D_INNER];
__device__ float g_P [ROWS * NPROJ];                // projection output
__device__ float g_Bv[ROWS * 64];
__device__ float g_Cv[ROWS * 64];
__device__ float g_Ad[ROWS * 64];
__device__ float g_ga[ROWS * 64];
__device__ float g_be[ROWS * 64];
__device__ float g_td[ROWS * 32];
__device__ float g_Y [ROWS * D_INNER];
__device__ float g_S [BATCH * NCHUNK * NHEADS * 64 * 64];
__device__ float g_eA[BATCH * NCHUNK * NHEADS * 64];
__device__ float g_cd[BATCH * NCHUNK * NHEADS];

__device__ __forceinline__ float siluf(float x) { return x / (1.f + expf(-x)); }

__device__ __forceinline__ uint32_t s2u(const void* p) {
    uint32_t a;
    asm("{ .reg .u64 t; cvta.to.shared.u64 t, %1; cvt.u32.u64 %0, t; }" : "=r"(a) : "l"(p));
    return a;
}

// ================= quant-aware emulated-fp32 GEMM via mma.sync =================
// C[M,Nw] = A[M,K] * B[N,K]^T where B = q * scale(group of 128 along K).
// A pre-split into bf16 hi/lo (2 MMA terms), q exact in bf16, scale folded in fp32
// at each 128-K group boundary.
// CTA 128x128, 8 warps (2x4) of 64x32 warp tiles, K-chunk 32, cp.async double buffer.
#define PADH 40                      // 32 halves + 8 pad
#define ARR_H (128*PADH)             // 5120 halves per sub-tile
#define BUF_H (3*ARR_H)              // Ah, Al, Bq
#define SS_OFF (2*BUF_H)             // halves offset where fp32 scales start

__device__ __forceinline__ void cpasync16(uint32_t dst, const void* src) {
    asm volatile("cp.async.cg.shared.global [%0], [%1], 16;" :: "r"(dst), "l"(src));
}
#define CP_COMMIT() asm volatile("cp.async.commit_group;" ::: "memory")
#define CP_WAIT1()  asm volatile("cp.async.wait_group 1;" ::: "memory")

#define LDSM4(r0,r1,r2,r3,a) \
    asm volatile("ldmatrix.sync.aligned.m8n8.x4.shared.b16 {%0,%1,%2,%3}, [%4];" \
        : "=r"(r0),"=r"(r1),"=r"(r2),"=r"(r3) : "r"(a))

#define MMA16816(d,a,b0,b1) \
    asm volatile("mma.sync.aligned.m16n8k16.row.col.f32.bf16.bf16.f32 " \
        "{%0,%1,%2,%3}, {%4,%5,%6,%7}, {%8,%9}, {%0,%1,%2,%3};" \
        : "+f"((d)[0]),"+f"((d)[1]),"+f"((d)[2]),"+f"((d)[3]) \
        : "r"((a)[0]),"r"((a)[1]),"r"((a)[2]),"r"((a)[3]),"r"(b0),"r"(b1))

template<int NG>
__global__ void __launch_bounds__(256, 1)
k_mmq(const __nv_bfloat16* __restrict__ Ah, const __nv_bfloat16* __restrict__ Al,
      const __nv_bfloat16* __restrict__ Bq, const float* __restrict__ Bs,
      float* __restrict__ C, int Nw, int Nlim, int K)
{
    extern __shared__ __nv_bfloat16 sh[];
    float* ss = (float*)(sh + SS_OFF);        // [NG][132] scales for this CTA's n-range
    const uint32_t sb = s2u(sh);
    const int tid  = threadIdx.x;
    const int lane = tid & 31;
    const int wid  = tid >> 5;
    const int m0 = blockIdx.x * 128;
    const int n0 = blockIdx.y * 128;
    const int mw = (wid >> 2) * 64;
    const int nw = (wid & 3) * 32;

    // preload scales for the CTA's 128 weight rows
    for (int idx = tid; idx < 128 * NG; idx += 256) {
        int g = idx >> 7, nl = idx & 127;
        ss[g * 132 + nl] = Bs[(size_t)(n0 + nl) * NG + g];
    }

    float acc[4][4][4];
#pragma unroll
    for (int i = 0; i < 4; i++)
#pragma unroll
        for (int j = 0; j < 4; j++)
#pragma unroll
            for (int k = 0; k < 4; k++) acc[i][j][k] = 0.f;

    const int NK = K >> 5;

#define FILLQ(buf, kc) do {                                                      \
        int kb = (kc) * 32;                                                      \
_Pragma("unroll")                                                                \
        for (int i = 0; i < 6; i++) {                                            \
            int idx = i * 256 + tid;                                             \
            int arr = idx >> 9;                                                  \
            int r   = (idx >> 2) & 127;                                          \
            int c   = idx & 3;                                                   \
            const __nv_bfloat16* sp = (arr == 0) ? (Ah + (size_t)(m0 + r) * K)   \
                                    : (arr == 1) ? (Al + (size_t)(m0 + r) * K)   \
                                                 : (Bq + (size_t)(n0 + r) * K);  \
            uint32_t dp = sb + ((buf) * BUF_H + arr * ARR_H + r * PADH + c * 8) * 2; \
            cpasync16(dp, sp + kb + c * 8);                                      \
        }                                                                        \
    } while (0)

    FILLQ(0, 0);
    CP_COMMIT();

    const int rowoff = (lane & 7) + ((lane >> 3) & 1) * 8;
    const int coloff = (lane >> 4) * 8;
    const int c0 = (lane & 3) * 2;

    for (int g = 0; g < NG; g++) {
        float accg[4][4][4];
#pragma unroll
        for (int i = 0; i < 4; i++)
#pragma unroll
            for (int j = 0; j < 4; j++)
#pragma unroll
                for (int k = 0; k < 4; k++) accg[i][j][k] = 0.f;

#pragma unroll
        for (int kq = 0; kq < 4; kq++) {
            const int kc = g * 4 + kq;
            const int buf = kc & 1;
            if (kc + 1 < NK) FILLQ(buf ^ 1, kc + 1);
            CP_COMMIT();
            CP_WAIT1();
            __syncthreads();

#pragma unroll
            for (int kk = 0; kk < 2; kk++) {
                uint32_t afr[2][4][4];
                uint32_t bfr[2][4];
#pragma unroll
                for (int hl = 0; hl < 2; hl++)
#pragma unroll
                    for (int mi = 0; mi < 4; mi++) {
                        uint32_t a = sb + (buf * BUF_H + hl * ARR_H +
                            (mw + mi * 16 + rowoff) * PADH + kk * 16 + coloff) * 2;
                        LDSM4(afr[hl][mi][0], afr[hl][mi][1], afr[hl][mi][2], afr[hl][mi][3], a);
                    }
#pragma unroll
                for (int nj = 0; nj < 2; nj++) {
                    uint32_t a = sb + (buf * BUF_H + 2 * ARR_H +
                        (nw + nj * 16 + rowoff) * PADH + kk * 16 + coloff) * 2;
                    LDSM4(bfr[nj][0], bfr[nj][1], bfr[nj][2], bfr[nj][3], a);
                }
#pragma unroll
                for (int term = 0; term < 2; term++)
#pragma unroll
                    for (int mi = 0; mi < 4; mi++)
#pragma unroll
                        for (int ni = 0; ni < 4; ni++) {
                            int nj = ni >> 1, s = ni & 1;
                            MMA16816(accg[mi][ni], afr[term][mi],
                                     bfr[nj][s], bfr[nj][s + 2]);
                        }
            }
            __syncthreads();
        }

        // fold group scales (per output column n)
#pragma unroll
        for (int ni = 0; ni < 4; ni++) {
            float2 sv = *(const float2*)&ss[g * 132 + nw + ni * 8 + c0];
#pragma unroll
            for (int mi = 0; mi < 4; mi++) {
                acc[mi][ni][0] = fmaf(sv.x, accg[mi][ni][0], acc[mi][ni][0]);
                acc[mi][ni][1] = fmaf(sv.y, accg[mi][ni][1], acc[mi][ni][1]);
                acc[mi][ni][2] = fmaf(sv.x, accg[mi][ni][2], acc[mi][ni][2]);
                acc[mi][ni][3] = fmaf(sv.y, accg[mi][ni][3], acc[mi][ni][3]);
            }
        }
    }

    // epilogue
    const int r0 = lane >> 2;
#pragma unroll
    for (int mi = 0; mi < 4; mi++) {
#pragma unroll
        for (int ni = 0; ni < 4; ni++) {
            int m = m0 + mw + mi * 16 + r0;
            int n = n0 + nw + ni * 8 + c0;
            if (n < Nlim) {
                *(float2*)&C[(size_t)m * Nw + n]       = make_float2(acc[mi][ni][0], acc[mi][ni][1]);
                *(float2*)&C[(size_t)(m + 8) * Nw + n] = make_float2(acc[mi][ni][2], acc[mi][ni][3]);
            }
        }
    }
#undef FILLQ
}

// ---------------- fq4 dequantization -> q (bf16, exact) + group scale ----------------
__global__ void k_dequantq(const float* __restrict__ src, __nv_bfloat16* __restrict__ dq,
                           float* __restrict__ ds, int ngroups)
{
    int g = blockIdx.x * 4 + (threadIdx.x >> 5);
    if (g >= ngroups) return;
    int lane = threadIdx.x & 31;
    const float* s = src + (size_t)g * 128;
    float v[4];
    float m = 0.f;
#pragma unroll
    for (int i = 0; i < 4; i++) { v[i] = s[lane + 32*i]; m = fmaxf(m, fabsf(v[i])); }
#pragma unroll
    for (int o = 16; o; o >>= 1) m = fmaxf(m, __shfl_xor_sync(0xffffffffu, m, o));
    float scale = fmaxf(m, 1e-10f) / 7.0f;
    if (lane == 0) ds[g] = scale;
#pragma unroll
    for (int i = 0; i < 4; i++) {
        float q = rintf(v[i] / scale);
        q = fminf(fmaxf(q, -8.f), 7.f);
        dq[(size_t)g * 128 + lane + 32*i] = __float2bfloat16(q);  // exact (small int)
    }
}

// ---------------- split fp32 -> bf16 hi/lo ----------------
__global__ void k_split(const float* __restrict__ src, __nv_bfloat16* __restrict__ dh,
                        __nv_bfloat16* __restrict__ dl)
{
    size_t i = ((size_t)blockIdx.x * 256 + threadIdx.x) * 4;
    float4 v = *(const float4*)(src + i);
    float vv[4] = {v.x, v.y, v.z, v.w};
#pragma unroll
    for (int k = 0; k < 4; k++) {
        __nv_bfloat16 h = __float2bfloat16(vv[k]);
        dh[i + k] = h;
        dl[i + k] = __float2bfloat16(vv[k] - __bfloat162float(h));
    }
}

// ---------------- pointwise epilogue per (b,l) row: 64 threads ----------------
__global__ void k_point(const float* __restrict__ Bb, const float* __restrict__ Cb,
                        const float* __restrict__ Alog, const float* __restrict__ dtb)
{
    int row = blockIdx.x;
    int t = threadIdx.x;
    const float* pr = g_P + (size_t)row * NPROJ;
    __shared__ float red[6];

    float dtr = pr[OFF_DT + t] + dtb[t];
    float dt = (dtr > 20.f) ? dtr : log1pf(expf(dtr));
    float Ad = -expf(Alog[t]) * dt;
    float lam = 1.f / (1.f + expf(-pr[OFF_LAM + t]));
    g_Ad[row*64 + t] = Ad;
    g_ga[row*64 + t] = lam * dt;
    g_be[row*64 + t] = (1.f - lam) * dt * expf(Ad);

    float bv = pr[OFF_B + t];
    float cv = pr[OFF_C + t];

    float s0 = dt, s1 = bv*bv, s2 = cv*cv;
#pragma unroll
    for (int o = 16; o; o >>= 1) {
        s0 += __shfl_xor_sync(0xffffffffu, s0, o);
        s1 += __shfl_xor_sync(0xffffffffu, s1, o);
        s2 += __shfl_xor_sync(0xffffffffu, s2, o);
    }
    int w = t >> 5;
    if ((t & 31) == 0) { red[w*3+0] = s0; red[w*3+1] = s1; red[w*3+2] = s2; }
    __syncthreads();
    float dt_avg = (red[0] + red[3]) * (1.f/64.f);
    float rb = rsqrtf((red[1] + red[4]) * (1.f/64.f) + RMS_EPS);
    float rc = rsqrtf((red[2] + red[5]) * (1.f/64.f) + RMS_EPS);

    g_Bv[row*64 + t] = bv * rb + Bb[t];
    g_Cv[row*64 + t] = cv * rc + Cb[t];
    if (t < 32) g_td[row*32 + t] = pr[OFF_TH + t] * dt_avg;
}

// ---------------- cumsum of theta*dt_avg over L per (b, n) ----------------
__global__ void k_scan()
{
    int b = blockIdx.x >> 5;
    int n = blockIdx.x & 31;
    int tid = threadIdx.x;
    __shared__ float ps[256];
    float loc[16];
    float run = 0.f;
    int base = (b*SEQ + tid*16) * 32 + n;
#pragma unroll
    for (int j = 0; j < 16; j++) { run += g_td[base + j*32]; loc[j] = run; }
    ps[tid] = run;
    __syncthreads();
#pragma unroll
    for (int o = 1; o < 256; o <<= 1) {
        float v = (tid >= o) ? ps[tid - o] : 0.f;
        __syncthreads();
        ps[tid] += v;
        __syncthreads();
    }
    float off = (tid > 0) ? ps[tid - 1] : 0.f;
#pragma unroll
    for (int j = 0; j < 16; j++) g_td[base + j*32] = loc[j] + off;
}

// ---------------- rope on B and C (in place) ----------------
__global__ void k_rope()
{
    int row = blockIdx.x;
    int t = threadIdx.x;
    float a = g_td[row*32 + t];
    float ca = cosf(a), sa = sinf(a);
    float br = g_Bv[row*64 + t], bi = g_Bv[row*64 + 32 + t];
    g_Bv[row*64 + t]      = br*ca - bi*sa;
    g_Bv[row*64 + 32 + t] = br*sa + bi*ca;
    float cr = g_Cv[row*64 + t], ci = g_Cv[row*64 + 32 + t];
    g_Cv[row*64 + t]      = cr*ca - ci*sa;
    g_Cv[row*64 + 32 + t] = cr*sa + ci*ca;
}

// ---------------- intra-chunk: Y_diag + per-chunk states ----------------
#define SM_CHUNK_BYTES ((4352*5 + 128) * 4)
__launch_bounds__(256)
__global__ void k_chunk()
{
    extern __shared__ float sm[];
    float* sX  = sm;
    float* sB  = sm + 4352;
    float* sBT = sm + 8704;
    float* sCT = sm + 13056;
    float* sGT = sm + 17408;
    float* sA  = sm + 21760;
    float* sW  = sm + 21824;

    const int h = blockIdx.x, c = blockIdx.y, b = blockIdx.z;
    const int tid = threadIdx.x;

    if (tid < 64) {
        int row_g = b*SEQ + c*64 + tid;
        sA[tid] = g_Ad[row_g*64 + h];
    }
    __syncthreads();
#pragma unroll
    for (int o = 1; o < 64; o <<= 1) {
        float v = (tid < 64 && tid >= o) ? sA[tid - o] : 0.f;
        __syncthreads();
        if (tid < 64) sA[tid] += v;
        __syncthreads();
    }
    float Alast = sA[63];
    if (tid < 64) {
        sW[tid] = expf(Alast - sA[tid]);
        g_eA[((b*NCHUNK + c)*NHEADS + h)*64 + tid] = expf(sA[tid]);
    }
    if (tid == 0) g_cd[(b*NCHUNK + c)*NHEADS + h] = expf(Alast);

#pragma unroll
    for (int it = 0; it < 4; it++) {
        int idx = tid + it*256;
        int l = idx >> 4;
        int p4 = (idx & 15) << 2;
        int row_g = b*SEQ + c*64 + l;
        const float* xp = g_P + (size_t)row_g*NPROJ + OFF_XC + h*64 + p4;
        float4 xc = *(const float4*)xp;
        float ga = g_ga[row_g*64 + h];
        float be = g_be[row_g*64 + h];
        float4 xv;
        xv.x = siluf(xc.x)*ga; xv.y = siluf(xc.y)*ga; xv.z = siluf(xc.z)*ga; xv.w = siluf(xc.w)*ga;
        if (c*64 + l > 0) {
            float4 xq = *(const float4*)(xp - NPROJ);
            xv.x += siluf(xq.x)*be; xv.y += siluf(xq.y)*be; xv.z += siluf(xq.z)*be; xv.w += siluf(xq.w)*be;
        }
        *(float4*)&sX[l*68 + p4] = xv;
        float4 bb = *(const float4*)&g_Bv[row_g*64 + p4];
        *(float4*)&sB[l*68 + p4] = bb;
        sBT[(p4+0)*68 + l] = bb.x; sBT[(p4+1)*68 + l] = bb.y;
        sBT[(p4+2)*68 + l] = bb.z; sBT[(p4+3)*68 + l] = bb.w;
        float4 cc = *(const float4*)&g_Cv[row_g*64 + p4];
        sCT[(p4+0)*68 + l] = cc.x; sCT[(p4+1)*68 + l] = cc.y;
        sCT[(p4+2)*68 + l] = cc.z; sCT[(p4+3)*68 + l] = cc.w;
    }
    __syncthreads();

    const int ti = tid >> 4, tj = tid & 15;

    {
        const int l0 = ti*4, s0 = tj*4;
        float acc[4][4];
#pragma unroll
        for (int i = 0; i < 4; i++)
#pragma unroll
            for (int j = 0; j < 4; j++) acc[i][j] = 0.f;
#pragma unroll
        for (int n = 0; n < 64; n++) {
            float4 cl = *(const float4*)&sCT[n*68 + l0];
            float4 bs = *(const float4*)&sBT[n*68 + s0];
            float clv[4] = {cl.x, cl.y, cl.z, cl.w};
            float bsv[4] = {bs.x, bs.y, bs.z, bs.w};
#pragma unroll
            for (int i = 0; i < 4; i++)
#pragma unroll
                for (int j = 0; j < 4; j++)
                    acc[i][j] = fmaf(clv[i], bsv[j], acc[i][j]);
        }
        float al[4];
#pragma unroll
        for (int i = 0; i < 4; i++) al[i] = sA[l0 + i];
#pragma unroll
        for (int j = 0; j < 4; j++) {
            int s = s0 + j;
            float as = sA[s];
#pragma unroll
            for (int i = 0; i < 4; i++) {
                int l = l0 + i;
                sGT[s*68 + l] = (s <= l) ? acc[i][j] * expf(al[i] - as) : 0.f;
            }
        }
    }
    __syncthreads();

    {
        const int l0 = ti*4, p0 = tj*4;
        float acc[4][4];
#pragma unroll
        for (int i = 0; i < 4; i++)
#pragma unroll
            for (int j = 0; j < 4; j++) acc[i][j] = 0.f;
#pragma unroll
        for (int s = 0; s < 64; s++) {
            float4 gt = *(const float4*)&sGT[s*68 + l0];
            float4 xr = *(const float4*)&sX[s*68 + p0];
            float gv[4] = {gt.x, gt.y, gt.z, gt.w};
            float xvv[4] = {xr.x, xr.y, xr.z, xr.w};
#pragma unroll
            for (int i = 0; i < 4; i++)
#pragma unroll
                for (int j = 0; j < 4; j++)
                    acc[i][j] = fmaf(gv[i], xvv[j], acc[i][j]);
        }
#pragma unroll
        for (int i = 0; i < 4; i++) {
            int row_g = b*SEQ + c*64 + l0 + i;
            *(float4*)&g_Y[(size_t)row_g*D_INNER + h*64 + p0] =
                make_float4(acc[i][0], acc[i][1], acc[i][2], acc[i][3]);
        }
    }

    {
        const int p0 = ti*4, n0 = tj*4;
        float acc[4][4];
#pragma unroll
        for (int i = 0; i < 4; i++)
#pragma unroll
            for (int j = 0; j < 4; j++) acc[i][j] = 0.f;
#pragma unroll
        for (int l = 0; l < 64; l++) {
            float w = sW[l];
            float4 xr = *(const float4*)&sX[l*68 + p0];
            float4 br = *(const float4*)&sB[l*68 + n0];
            float wx[4] = {w*xr.x, w*xr.y, w*xr.z, w*xr.w};
            float bvv[4] = {br.x, br.y, br.z, br.w};
#pragma unroll
            for (int i = 0; i < 4; i++)
#pragma unroll
                for (int j = 0; j < 4; j++)
                    acc[i][j] = fmaf(wx[i], bvv[j], acc[i][j]);
        }
        size_t base = (size_t)((b*NCHUNK + c)*NHEADS + h) * 4096;
#pragma unroll
        for (int i = 0; i < 4; i++)
            *(float4*)&g_S[base + (p0 + i)*64 + n0] =
                make_float4(acc[i][0], acc[i][1], acc[i][2], acc[i][3]);
    }
}

// ---------------- inter-chunk scan ----------------
__global__ void k_cscan()
{
    int b = blockIdx.x >> 6;
    int h = blockIdx.x & 63;
    int tid = threadIdx.x;
    float s[16];
#pragma unroll
    for (int i = 0; i < 16; i++) s[i] = 0.f;
    for (int c = 0; c < NCHUNK; c++) {
        size_t base = (size_t)((b*NCHUNK + c)*NHEADS + h) * 4096 + tid*16;
        float cd = g_cd[(b*NCHUNK + c)*NHEADS + h];
        float4 t0 = *(const float4*)&g_S[base + 0];
        float4 t1 = *(const float4*)&g_S[base + 4];
        float4 t2 = *(const float4*)&g_S[base + 8];
        float4 t3 = *(const float4*)&g_S[base + 12];
        *(float4*)&g_S[base + 0]  = make_float4(s[0],  s[1],  s[2],  s[3]);
        *(float4*)&g_S[base + 4]  = make_float4(s[4],  s[5],  s[6],  s[7]);
        *(float4*)&g_S[base + 8]  = make_float4(s[8],  s[9],  s[10], s[11]);
        *(float4*)&g_S[base + 12] = make_float4(s[12], s[13], s[14], s[15]);
        s[0]  = fmaf(cd, s[0],  t0.x); s[1]  = fmaf(cd, s[1],  t0.y);
        s[2]  = fmaf(cd, s[2],  t0.z); s[3]  = fmaf(cd, s[3],  t0.w);
        s[4]  = fmaf(cd, s[4],  t1.x); s[5]  = fmaf(cd, s[5],  t1.y);
        s[6]  = fmaf(cd, s[6],  t1.z); s[7]  = fmaf(cd, s[7],  t1.w);
        s[8]  = fmaf(cd, s[8],  t2.x); s[9]  = fmaf(cd, s[9],  t2.y);
        s[10] = fmaf(cd, s[10], t2.z); s[11] = fmaf(cd, s[11], t2.w);
        s[12] = fmaf(cd, s[12], t3.x); s[13] = fmaf(cd, s[13], t3.y);
        s[14] = fmaf(cd, s[14], t3.z); s[15] = fmaf(cd, s[15], t3.w);
    }
}

// ---------------- Y_off + D skip + z gating ----------------
__launch_bounds__(256)
__global__ void k_off(const float* __restrict__ Dp)
{
    __shared__ float sST[64*68];
    __shared__ float sCT[64*68];
    const int h = blockIdx.x, c = blockIdx.y, b = blockIdx.z;
    const int tid = threadIdx.x;
    size_t sbase = (size_t)((b*NCHUNK + c)*NHEADS + h) * 4096;
#pragma unroll
    for (int it = 0; it < 4; it++) {
        int idx = tid + it*256;
        int r = idx >> 4;
        int n4 = (idx & 15) << 2;
        float4 sv = *(const float4*)&g_S[sbase + r*64 + n4];
        sST[(n4+0)*68 + r] = sv.x; sST[(n4+1)*68 + r] = sv.y;
        sST[(n4+2)*68 + r] = sv.z; sST[(n4+3)*68 + r] = sv.w;
        int row_g = b*SEQ + c*64 + r;
        float4 cv = *(const float4*)&g_Cv[row_g*64 + n4];
        sCT[(n4+0)*68 + r] = cv.x; sCT[(n4+1)*68 + r] = cv.y;
        sCT[(n4+2)*68 + r] = cv.z; sCT[(n4+3)*68 + r] = cv.w;
    }
    __syncthreads();
    const int ti = tid >> 4, tj = tid & 15;
    const int l0 = ti*4, p0 = tj*4;
    float acc[4][4];
#pragma unroll
    for (int i = 0; i < 4; i++)
#pragma unroll
        for (int j = 0; j < 4; j++) acc[i][j] = 0.f;
#pragma unroll
    for (int n = 0; n < 64; n++) {
        float4 cl = *(const float4*)&sCT[n*68 + l0];
        float4 sp = *(const float4*)&sST[n*68 + p0];
        float clv[4] = {cl.x, cl.y, cl.z, cl.w};
        float spv[4] = {sp.x, sp.y, sp.z, sp.w};
#pragma unroll
        for (int i = 0; i < 4; i++)
#pragma unroll
            for (int j = 0; j < 4; j++)
                acc[i][j] = fmaf(clv[i], spv[j], acc[i][j]);
    }
    float Dh = Dp[h];
#pragma unroll
    for (int i = 0; i < 4; i++) {
        int l = l0 + i;
        int row_g = b*SEQ + c*64 + l;
        float e = g_eA[((b*NCHUNK + c)*NHEADS + h)*64 + l];
        const float* pr = g_P + (size_t)row_g*NPROJ;
        float4 xc = *(const float4*)&pr[OFF_XC + h*64 + p0];
        float4 zz = *(const float4*)&pr[OFF_Z  + h*64 + p0];
        float* yp = &g_Y[(size_t)row_g*D_INNER + h*64 + p0];
        float4 yd = *(const float4*)yp;
        float4 o;
        o.x = (yd.x + e*acc[i][0] + Dh*siluf(xc.x)) * siluf(zz.x);
        o.y = (yd.y + e*acc[i][1] + Dh*siluf(xc.y)) * siluf(zz.y);
        o.z = (yd.z + e*acc[i][2] + Dh*siluf(xc.z)) * siluf(zz.z);
        o.w = (yd.w + e*acc[i][3] + Dh*siluf(xc.w)) * siluf(zz.w);
        *(float4*)yp = o;
    }
}

// ---------------- rmsnorm over 4096 per row -> bf16 hi/lo ----------------
__global__ void k_rms()
{
    int row = blockIdx.x;
    int tid = threadIdx.x;
    const float* Yp = g_Y + (size_t)row * D_INNER;
    float4 v[4];
    float ss = 0.f;
#pragma unroll
    for (int i = 0; i < 4; i++) {
        v[i] = *(const float4*)&Yp[tid*16 + i*4];
        ss += v[i].x*v[i].x + v[i].y*v[i].y + v[i].z*v[i].z + v[i].w*v[i].w;
    }
#pragma unroll
    for (int o = 16; o; o >>= 1) ss += __shfl_xor_sync(0xffffffffu, ss, o);
    __shared__ float red[8];
    if ((tid & 31) == 0) red[tid >> 5] = ss;
    __syncthreads();
    float tot = 0.f;
#pragma unroll
    for (int i = 0; i < 8; i++) tot += red[i];
    float r = rsqrtf(tot * (1.f/4096.f) + RMS_EPS);
    size_t base = (size_t)row * D_INNER + tid*16;
#pragma unroll
    for (int i = 0; i < 4; i++) {
        float vv[4] = {v[i].x*r, v[i].y*r, v[i].z*r, v[i].w*r};
#pragma unroll
        for (int k = 0; k < 4; k++) {
            __nv_bfloat16 h = __float2bfloat16(vv[k]);
            g_Yh[base + i*4 + k] = h;
            g_Yl[base + i*4 + k] = __float2bfloat16(vv[k] - __bfloat162float(h));
        }
    }
}

// ---------------- launcher ----------------
extern "C" void kernel_launch(void* const* d_in, const int* in_sizes, int n_in,
                              void* d_out, int out_size)
{
    const float* x    = (const float*)d_in[0];
    const float* Win  = (const float*)d_in[1];
    const float* Wth  = (const float*)d_in[2];
    const float* Wla  = (const float*)d_in[3];
    const float* Wout = (const float*)d_in[4];
    const float* Bb   = (const float*)d_in[5];
    const float* Cb   = (const float*)d_in[6];
    const float* Alog = (const float*)d_in[7];
    const float* Dp   = (const float*)d_in[8];
    const float* dtb  = (const float*)d_in[9];
    float* out = (float*)d_out;

    __nv_bfloat16 *pWq, *pWoq, *pxh, *pxl, *pYh, *pYl;
    float *pWs, *pWos, *pP;
    cudaGetSymbolAddress((void**)&pWq,  g_Wq);
    cudaGetSymbolAddress((void**)&pWs,  g_Ws);
    cudaGetSymbolAddress((void**)&pWoq, g_Woq);
    cudaGetSymbolAddress((void**)&pWos, g_Wos);
    cudaGetSymbolAddress((void**)&pxh,  g_xh);
    cudaGetSymbolAddress((void**)&pxl,  g_xl);
    cudaGetSymbolAddress((void**)&pYh,  g_Yh);
    cudaGetSymbolAddress((void**)&pYl,  g_Yl);
    cudaGetSymbolAddress((void**)&pP,   g_P);

    const int smem1 = (SS_OFF * 2) + 16 * 132 * 4;   // 61440 + 8448
    const int smem2 = (SS_OFF * 2) + 32 * 132 * 4;   // 61440 + 16896

    cudaFuncSetAttribute(k_chunk,    cudaFuncAttributeMaxDynamicSharedMemorySize, SM_CHUNK_BYTES);
    cudaFuncSetAttribute(k_mmq<16>,  cudaFuncAttributeMaxDynamicSharedMemorySize, smem1);
    cudaFuncSetAttribute(k_mmq<32>,  cudaFuncAttributeMaxDynamicSharedMemorySize, smem2);

    // fq4 dequant -> q + scales into fused weight buffer (pad rows stay zero)
    k_dequantq<<<(8384*16 + 3)/4, 128>>>(Win, pWq, pWs, 8384*16);
    k_dequantq<<<(512 + 3)/4,    128>>>(Wth, pWq + (size_t)8384*DIMK, pWs + (size_t)8384*16, 512);
    k_dequantq<<<(1024 + 3)/4,   128>>>(Wla, pWq + (size_t)8416*DIMK, pWs + (size_t)8416*16, 1024);
    k_dequantq<<<65536/4,        128>>>(Wout, pWoq, pWos, 65536);

    // split activations
    k_split<<<ROWS*DIMK/1024, 256>>>(x, pxh, pxl);

    // in-projection GEMM: 8192 x 8480 x 2048 (2-term + group-scale fold)
    k_mmq<16><<<dim3(ROWS/128, NPROJ_PAD/128), 256, smem1>>>(
        pxh, pxl, pWq, pWs, pP, NPROJ, NPROJ, DIMK);

    k_point<<<ROWS, 64>>>(Bb, Cb, Alog, dtb);
    k_scan <<<64, 256>>>();
    k_rope <<<ROWS, 32>>>();

    k_chunk<<<dim3(NHEADS, NCHUNK, BATCH), 256, SM_CHUNK_BYTES>>>();
    k_cscan<<<128, 256>>>();
    k_off  <<<dim3(NHEADS, NCHUNK, BATCH), 256>>>(Dp);

    k_rms<<<ROWS, 256>>>();

    // out-projection GEMM: 8192 x 2048 x 4096 (2-term + group-scale fold)
    k_mmq<32><<<dim3(ROWS/128, DIMK/128), 256, smem2>>>(
        pYh, pYl, pWoq, pWos, out, DIMK, DIMK, D_INNER);
}